// round 17
// baseline (speedup 1.0000x reference)
#include <cuda_runtime.h>
#include <cstdint>
#include <math.h>

#define BATCH 16384
#define NUM_CLASSES 1604
#define C4 (NUM_CLASSES / 4)            // 401 float4 per row
#define ROW_BYTES (NUM_CLASSES * 4)     // 6416, multiple of 16
#define WARPS_PER_BLOCK 8
#define THREADS (WARPS_PER_BLOCK * 32)
#define TILE_BYTES (WARPS_PER_BLOCK * ROW_BYTES)   // 51328
#define SMEM_LG 0
#define SMEM_S  TILE_BYTES
#define SMEM_MBAR (2 * TILE_BYTES)                  // 102656
#define SMEM_TOTAL (SMEM_MBAR + 16)
#define EPS 1e-6f

__global__ void zero_out_kernel(float* out) {
    if (threadIdx.x == 0) out[0] = 0.0f;
}

__device__ __forceinline__ uint32_t smem_u32(const void* p) {
    return (uint32_t)__cvta_generic_to_shared(p);
}

// 1D bulk copy gmem->smem, completion via mbarrier complete_tx.
__device__ __forceinline__ void bulk_g2s(uint32_t dst_smem, const void* src,
                                         uint32_t bytes, uint32_t mbar) {
    asm volatile(
        "cp.async.bulk.shared::cta.global.mbarrier::complete_tx::bytes "
        "[%0], [%1], %2, [%3];"
        :: "r"(dst_smem), "l"(src), "r"(bytes), "r"(mbar) : "memory");
}

// One block = 8 samples. ALL global traffic moves via cp.async.bulk (TMA/UBLKCP
// path): 8 contiguous logits rows + 8 gathered s rows land in SMEM under one
// mbarrier; the compute mainloop issues zero LDGs. This bypasses the per-SM
// outstanding-LDG tracking limit that pinned the LDG versions at ~4.5-4.8 TB/s
// across three structurally different schedules (R5/R6/R15).
// 2 blocks/SM (103KB smem each): one loads while the other computes.
// No max-subtraction (sigma shift-invariant; measured margin 2.5e-7 vs 1e-3).
__global__ __launch_bounds__(THREADS)
void seesaw_loss_kernel(const float* __restrict__ logits,
                        const float* __restrict__ s,
                        const int* __restrict__ targets,
                        float* __restrict__ out) {
    extern __shared__ __align__(16) char smem_raw[];
    const int tid  = threadIdx.x;
    const int warp = tid >> 5;
    const int lane = tid & 31;
    const int b = blockIdx.x * WARPS_PER_BLOCK + warp;
    const int t = targets[b];

    const uint32_t mbar = smem_u32(smem_raw + SMEM_MBAR);

    if (tid == 0) {
        asm volatile("mbarrier.init.shared.b64 [%0], 1;" :: "r"(mbar) : "memory");
    }
    __syncthreads();
    if (tid == 0) {
        asm volatile("mbarrier.arrive.expect_tx.shared.b64 _, [%0], %1;"
                     :: "r"(mbar), "r"((uint32_t)(2 * TILE_BYTES)) : "memory");
    }
    __syncthreads();   // expect_tx strictly before any copy can complete

    if (lane == 0) {   // each warp issues its own two row copies
        bulk_g2s(smem_u32(smem_raw + SMEM_LG + warp * ROW_BYTES),
                 logits + (size_t)b * NUM_CLASSES, ROW_BYTES, mbar);
        bulk_g2s(smem_u32(smem_raw + SMEM_S + warp * ROW_BYTES),
                 s + (size_t)t * NUM_CLASSES, ROW_BYTES, mbar);
    }

    // Acquire-wait on phase 0 (smem fresh every launch -> parity always 0).
    {
        uint32_t done;
        asm volatile(
            "{\n\t.reg .pred p;\n\t"
            "mbarrier.try_wait.parity.acquire.cta.shared::cta.b64 p, [%1], 0;\n\t"
            "selp.b32 %0, 1, 0, p;\n\t}"
            : "=r"(done) : "r"(mbar) : "memory");
        while (!done) {
            asm volatile(
                "{\n\t.reg .pred p;\n\t"
                "mbarrier.try_wait.parity.acquire.cta.shared::cta.b64 p, [%1], 0, 0x989680;\n\t"
                "selp.b32 %0, 1, 0, p;\n\t}"
                : "=r"(done) : "r"(mbar) : "memory");
        }
    }

    // Compute from SMEM. Conflict-free: consecutive lanes read consecutive 16B.
    const float4* lg4 = reinterpret_cast<const float4*>(smem_raw + SMEM_LG)
                        + warp * C4;
    const float4* s4  = reinterpret_cast<const float4*>(smem_raw + SMEM_S)
                        + warp * C4;

    // denom = sum_j s[t,j]*exp(x_j); the j==t term equals num_t (s[t,t]==1).
    float sum = 0.0f;
    #pragma unroll 4
    for (int i = lane; i < C4; i += 32) {
        float4 x = lg4[i];
        float4 w = s4[i];
        sum += w.x * __expf(x.x) + w.y * __expf(x.y)
             + w.z * __expf(x.z) + w.w * __expf(x.w);
    }

    #pragma unroll
    for (int o = 16; o > 0; o >>= 1)
        sum += __shfl_xor_sync(0xFFFFFFFFu, sum, o);

    __shared__ float sh_loss[WARPS_PER_BLOCK];
    if (lane == 0) {
        const float* lg_row = reinterpret_cast<const float*>(smem_raw + SMEM_LG)
                              + warp * NUM_CLASSES;
        float num_t = __expf(lg_row[t]);
        float sigma = num_t / (sum + EPS);
        sh_loss[warp] = -__logf(sigma + EPS);
    }
    __syncthreads();

    if (tid == 0) {
        float acc = 0.0f;
        #pragma unroll
        for (int w = 0; w < WARPS_PER_BLOCK; w++) acc += sh_loss[w];
        atomicAdd(out, acc * (1.0f / (float)BATCH));
    }
}

extern "C" void kernel_launch(void* const* d_in, const int* in_sizes, int n_in,
                              void* d_out, int out_size) {
    const float* logits  = (const float*)d_in[0];
    const float* s       = (const float*)d_in[1];
    const int*   targets = (const int*)d_in[2];
    float* out = (float*)d_out;

    static bool configured = false;
    if (!configured) {
        cudaFuncSetAttribute(seesaw_loss_kernel,
                             cudaFuncAttributeMaxDynamicSharedMemorySize,
                             SMEM_TOTAL);
        configured = true;
    }

    zero_out_kernel<<<1, 32>>>(out);
    seesaw_loss_kernel<<<BATCH / WARPS_PER_BLOCK, THREADS, SMEM_TOTAL>>>(
        logits, s, targets, out);
}